// round 9
// baseline (speedup 1.0000x reference)
#include <cuda_runtime.h>
#include <cuda_bf16.h>
#include <math.h>
#include <stdint.h>

#define BB 4
#define TT 2048
#define DD 1024
#define HH 16
#define DH 64
#define MTOT (BB*TT)            // 8192
#define OUT0 (BB*TT*DD)         // 8388608 floats: "out" part of d_out

typedef unsigned long long ull;

// packed f32x2 helpers (Blackwell FFMA2 path)
#define FMA2(acc, a, b) \
    asm("fma.rn.f32x2 %0, %1, %2, %0;" : "+l"(acc) : "l"(a), "l"(b))
#define PACKD(out, f) \
    asm("mov.b64 %0, {%1, %1};" : "=l"(out) : "f"(f))
#define UNPACK2(lo, hi, in) \
    asm("mov.b64 {%0, %1}, %2;" : "=f"(lo), "=f"(hi) : "l"(in))

// Scratch (static device arrays; runtime alloc forbidden)
__device__ float g_q[BB*HH*TT*DH];
__device__ float g_k[BB*HH*TT*DH];
__device__ float g_v[BB*HH*TT*DH];
__device__ float g_ctx[BB*TT*DD];

// ---------------------------------------------------------------------------
// SGEMM: C[M,N] = A[M,K] @ B[K,N] + bias   (register-prefetch + FFMA2)
// MODE 0: A = g_ctx, plain row-major epilogue into C
// MODE 1: A = Ain (x), epilogue scatters into g_q/g_k/g_v in [b][h][t][dh]
// 128x128 tile, 16-deep K slices, 256 threads, 8x8 per-thread microtile.
// ---------------------------------------------------------------------------
template<int MODE>
__global__ __launch_bounds__(256)
void sgemm_k(const float* __restrict__ Ain, const float* __restrict__ Bw,
             const float* __restrict__ bias, float* __restrict__ C,
             int M, int N, int K) {
    __shared__ float As[16][132];   // transposed A tile: As[kk][m]
    __shared__ float Bs[16][132];   // natural B tile:    Bs[kk][n]

    const float* A = (MODE == 0) ? g_ctx : Ain;
    const int tid = threadIdx.x;
    const int tx = tid & 15, ty = tid >> 4;
    const int m0 = blockIdx.y * 128, n0 = blockIdx.x * 128;

    // per-thread load slots (fixed across slices)
    const int arow0 = (tid + 0) >> 2,        ac0 = ((tid + 0) & 3) * 4;
    const int arow1 = (tid + 256) >> 2,      ac1 = ((tid + 256) & 3) * 4;
    const int brow0 = (tid + 0) >> 5,        bc0 = ((tid + 0) & 31) * 4;
    const int brow1 = (tid + 256) >> 5,      bc1 = ((tid + 256) & 31) * 4;

    // packed accumulators: acc2[i][jp] holds cols (2jp, 2jp+1) of row i
    ull acc2[8][4];
    #pragma unroll
    for (int i = 0; i < 8; i++)
        #pragma unroll
        for (int j = 0; j < 4; j++) acc2[i][j] = 0ULL;

    // prefetch slice 0
    float4 pa0 = *reinterpret_cast<const float4*>(&A[(size_t)(m0 + arow0) * K + ac0]);
    float4 pa1 = *reinterpret_cast<const float4*>(&A[(size_t)(m0 + arow1) * K + ac1]);
    float4 pb0 = *reinterpret_cast<const float4*>(&Bw[(size_t)brow0 * N + n0 + bc0]);
    float4 pb1 = *reinterpret_cast<const float4*>(&Bw[(size_t)brow1 * N + n0 + bc1]);

    for (int k0 = 0; k0 < K; k0 += 16) {
        As[ac0 + 0][arow0] = pa0.x; As[ac0 + 1][arow0] = pa0.y;
        As[ac0 + 2][arow0] = pa0.z; As[ac0 + 3][arow0] = pa0.w;
        As[ac1 + 0][arow1] = pa1.x; As[ac1 + 1][arow1] = pa1.y;
        As[ac1 + 2][arow1] = pa1.z; As[ac1 + 3][arow1] = pa1.w;
        *reinterpret_cast<float4*>(&Bs[brow0][bc0]) = pb0;
        *reinterpret_cast<float4*>(&Bs[brow1][bc1]) = pb1;
        __syncthreads();

        if (k0 + 16 < K) {
            pa0 = *reinterpret_cast<const float4*>(&A[(size_t)(m0 + arow0) * K + k0 + 16 + ac0]);
            pa1 = *reinterpret_cast<const float4*>(&A[(size_t)(m0 + arow1) * K + k0 + 16 + ac1]);
            pb0 = *reinterpret_cast<const float4*>(&Bw[(size_t)(k0 + 16 + brow0) * N + n0 + bc0]);
            pb1 = *reinterpret_cast<const float4*>(&Bw[(size_t)(k0 + 16 + brow1) * N + n0 + bc1]);
        }

        #pragma unroll
        for (int kk = 0; kk < 16; kk++) {
            float a[8];
            *reinterpret_cast<float4*>(&a[0]) = *reinterpret_cast<float4*>(&As[kk][ty * 8]);
            *reinterpret_cast<float4*>(&a[4]) = *reinterpret_cast<float4*>(&As[kk][ty * 8 + 4]);
            // B col-pairs read natively as packed 64-bit lanes (16B-aligned)
            ulonglong2 b01 = *reinterpret_cast<ulonglong2*>(&Bs[kk][tx * 8]);
            ulonglong2 b23 = *reinterpret_cast<ulonglong2*>(&Bs[kk][tx * 8 + 4]);
            #pragma unroll
            for (int i = 0; i < 8; i++) {
                ull da;
                PACKD(da, a[i]);
                FMA2(acc2[i][0], da, b01.x);
                FMA2(acc2[i][1], da, b01.y);
                FMA2(acc2[i][2], da, b23.x);
                FMA2(acc2[i][3], da, b23.y);
            }
        }
        __syncthreads();
    }

    // unpack to the scalar layout the proven epilogues expect
    float acc[8][8];
    #pragma unroll
    for (int i = 0; i < 8; i++)
        #pragma unroll
        for (int jp = 0; jp < 4; jp++)
            UNPACK2(acc[i][2 * jp], acc[i][2 * jp + 1], acc2[i][jp]);

    if (MODE == 0) {
        #pragma unroll
        for (int i = 0; i < 8; i++) {
            int row = m0 + ty * 8 + i;
            #pragma unroll
            for (int j0 = 0; j0 < 8; j0 += 4) {
                int col = n0 + tx * 8 + j0;
                float4 v;
                v.x = acc[i][j0 + 0] + bias[col + 0];
                v.y = acc[i][j0 + 1] + bias[col + 1];
                v.z = acc[i][j0 + 2] + bias[col + 2];
                v.w = acc[i][j0 + 3] + bias[col + 3];
                *reinterpret_cast<float4*>(&C[(size_t)row * N + col]) = v;
            }
        }
    } else {
        #pragma unroll
        for (int i = 0; i < 8; i++) {
            int row = m0 + ty * 8 + i;
            int bb = row >> 11, t = row & 2047;
            #pragma unroll
            for (int j = 0; j < 8; j++) {
                int n = n0 + tx * 8 + j;
                int which = n >> 10;
                int rem = n & 1023;
                int h = rem >> 6, dh = rem & 63;
                float v = acc[i][j] + bias[n];
                float* dst = (which == 0) ? g_q : (which == 1) ? g_k : g_v;
                dst[(((size_t)(bb * HH + h)) * TT + t) * DH + dh] = v;
            }
        }
    }
}

// ---------------------------------------------------------------------------
// Attention: one block per (b, h, 16-query tile). Full 16x2048 score strip in
// smem -> exact softmax, weights written once, context from smem scores.
// Same structure as the 4103us kernel; inner products use FFMA2.
// ---------------------------------------------------------------------------
#define SM_QS   0                       // [16][64]
#define SM_KT   1024                    // [64][128] swizzled float4 columns
#define SM_VB   (1024 + 8192)           // [128][68]
#define SM_SS   (1024 + 8192 + 8704)    // [16][2048]
#define ATTN_SMEM_FLOATS (1024 + 8192 + 8704 + 32768)
#define ATTN_SMEM_BYTES  (ATTN_SMEM_FLOATS * 4)   // 202752

__global__ __launch_bounds__(256)
void attn_kernel(float* __restrict__ wout) {
    extern __shared__ float sm[];
    float* qs = sm + SM_QS;
    float* kT = sm + SM_KT;
    float* vb = sm + SM_VB;
    float* sS = sm + SM_SS;

    const int tid = threadIdx.x;
    const int qt = blockIdx.x, h = blockIdx.y, b = blockIdx.z;
    const int q0 = qt * 16;
    const size_t hb = ((size_t)(b * HH + h)) * TT;

    // ---- load Q tile, pre-scaled by 1/sqrt(64) = 0.125 ----
    {
        int r = tid >> 4, c = (tid & 15) * 4;
        float4 v = *reinterpret_cast<const float4*>(&g_q[(hb + q0 + r) * DH + c]);
        qs[r * 64 + c + 0] = v.x * 0.125f;
        qs[r * 64 + c + 1] = v.y * 0.125f;
        qs[r * 64 + c + 2] = v.z * 0.125f;
        qs[r * 64 + c + 3] = v.w * 0.125f;
    }

    const int nch = (q0 + 16 + 127) >> 7;   // 128-key chunks covering causal span
    const int Lc = nch << 7;

    // ---- phase 1: scores -> sS (masked with -1e30) ----
    {
        const int rg = tid >> 5;     // 8 row groups of 2 rows
        const int cg = tid & 31;     // 32 col groups of 4 keys
        for (int c = 0; c < nch; c++) {
            const int kb = c << 7;
            __syncthreads();   // kT reuse safe / qs ready on first iter
            #pragma unroll
            for (int i = 0; i < 2; i++) {
                int gid = tid + i * 256;
                int kq = gid >> 4, c4 = gid & 15;
                float vr[4][4];
                #pragma unroll
                for (int jj = 0; jj < 4; jj++) {
                    float4 t4 = *reinterpret_cast<const float4*>(
                        &g_k[(hb + kb + kq * 4 + jj) * DH + c4 * 4]);
                    vr[jj][0] = t4.x; vr[jj][1] = t4.y;
                    vr[jj][2] = t4.z; vr[jj][3] = t4.w;
                }
                #pragma unroll
                for (int dd = 0; dd < 4; dd++) {
                    int row = c4 * 4 + dd;
                    int p = kq ^ (row & 31);
                    *reinterpret_cast<float4*>(&kT[row * 128 + p * 4]) =
                        make_float4(vr[0][dd], vr[1][dd], vr[2][dd], vr[3][dd]);
                }
            }
            __syncthreads();
            ull acc2[2][2];
            acc2[0][0] = 0ULL; acc2[0][1] = 0ULL;
            acc2[1][0] = 0ULL; acc2[1][1] = 0ULL;
            #pragma unroll
            for (int kk = 0; kk < 64; kk++) {
                float qa = qs[(rg * 2 + 0) * 64 + kk];
                float qb = qs[(rg * 2 + 1) * 64 + kk];
                ull dqa, dqb;
                PACKD(dqa, qa);
                PACKD(dqb, qb);
                ulonglong2 kvp = *reinterpret_cast<const ulonglong2*>(
                    &kT[kk * 128 + (cg ^ (kk & 31)) * 4]);
                FMA2(acc2[0][0], dqa, kvp.x);
                FMA2(acc2[0][1], dqa, kvp.y);
                FMA2(acc2[1][0], dqb, kvp.x);
                FMA2(acc2[1][1], dqb, kvp.y);
            }
            float av[2][4];
            #pragma unroll
            for (int i = 0; i < 2; i++) {
                UNPACK2(av[i][0], av[i][1], acc2[i][0]);
                UNPACK2(av[i][2], av[i][3], acc2[i][1]);
            }
            #pragma unroll
            for (int i = 0; i < 2; i++) {
                int row = rg * 2 + i;
                int qg = q0 + row;
                int kbase = kb + cg * 4;
                float4 o;
                o.x = (kbase + 0 <= qg) ? av[i][0] : -1e30f;
                o.y = (kbase + 1 <= qg) ? av[i][1] : -1e30f;
                o.z = (kbase + 2 <= qg) ? av[i][2] : -1e30f;
                o.w = (kbase + 3 <= qg) ? av[i][3] : -1e30f;
                *reinterpret_cast<float4*>(&sS[row * 2048 + kbase]) = o;
            }
        }
    }
    __syncthreads();

    // ---- phase 2: exact softmax, write weights (+ zero masked tail) ----
    {
        const int warp = tid >> 5, lane = tid & 31;
        for (int i = warp; i < 16; i += 8) {
            float* row = &sS[i * 2048];
            float mx = -1e30f;
            for (int j = lane; j < Lc; j += 32) mx = fmaxf(mx, row[j]);
            #pragma unroll
            for (int o = 16; o; o >>= 1) mx = fmaxf(mx, __shfl_xor_sync(0xffffffffu, mx, o));
            float s = 0.f;
            for (int j = lane; j < Lc; j += 32) {
                float e = __expf(row[j] - mx);
                row[j] = e; s += e;
            }
            #pragma unroll
            for (int o = 16; o; o >>= 1) s += __shfl_xor_sync(0xffffffffu, s, o);
            float inv = 1.0f / s;
            float* wr = &wout[(hb + q0 + i) * TT];
            for (int j = lane; j < Lc; j += 32) {
                float w = row[j] * inv;
                row[j] = w;
                wr[j] = w;
            }
            for (int j = Lc + lane; j < TT; j += 32) wr[j] = 0.f;
        }
    }
    __syncthreads();

    // ---- phase 3: context = W @ V  (FFMA2 inner product) ----
    {
        const int r = tid >> 4, dg = tid & 15;
        ull ap0 = 0ULL, ap1 = 0ULL;
        for (int c = 0; c < nch; c++) {
            const int kb = c << 7;
            __syncthreads();   // vb reuse safe
            #pragma unroll
            for (int i = 0; i < 8; i++) {
                int idx = tid + i * 256;
                int key = idx >> 4, c4 = (idx & 15) * 4;
                *reinterpret_cast<float4*>(&vb[key * 68 + c4]) =
                    *reinterpret_cast<const float4*>(
                        &g_v[(hb + kb + key) * DH + c4]);
            }
            __syncthreads();
            #pragma unroll 4
            for (int j = 0; j < 128; j++) {
                float w = sS[r * 2048 + kb + j];
                ull dw;
                PACKD(dw, w);
                ulonglong2 vp = *reinterpret_cast<const ulonglong2*>(
                    &vb[j * 68 + dg * 4]);
                FMA2(ap0, dw, vp.x);
                FMA2(ap1, dw, vp.y);
            }
        }
        float a0, a1, a2, a3;
        UNPACK2(a0, a1, ap0);
        UNPACK2(a2, a3, ap1);
        *reinterpret_cast<float4*>(
            &g_ctx[((size_t)(b * TT + q0 + r)) * DD + h * 64 + dg * 4]) =
            make_float4(a0, a1, a2, a3);
    }
}

// ---------------------------------------------------------------------------
extern "C" void kernel_launch(void* const* d_in, const int* in_sizes, int n_in,
                              void* d_out, int out_size) {
    const float* x     = (const float*)d_in[0];
    const float* w_qkv = (const float*)d_in[1];
    const float* b_qkv = (const float*)d_in[2];
    const float* w_out = (const float*)d_in[3];
    const float* b_out = (const float*)d_in[4];
    float* out     = (float*)d_out;          // (B,T,D)
    float* weights = out + OUT0;             // (B,H,T,T)

    (void)in_sizes; (void)n_in; (void)out_size;

    cudaFuncSetAttribute(attn_kernel,
                         cudaFuncAttributeMaxDynamicSharedMemorySize,
                         ATTN_SMEM_BYTES);

    // 1) QKV projection, scattered into per-head Q/K/V layout
    sgemm_k<1><<<dim3(3 * DD / 128, MTOT / 128), 256>>>(
        x, w_qkv, b_qkv, nullptr, MTOT, 3 * DD, DD);

    // 2) causal attention: weights out + context
    attn_kernel<<<dim3(TT / 16, HH, BB), 256, ATTN_SMEM_BYTES>>>(weights);

    // 3) output projection
    sgemm_k<0><<<dim3(DD / 128, MTOT / 128), 256>>>(
        nullptr, w_out, b_out, out, MTOT, DD, DD);
}